// round 17
// baseline (speedup 1.0000x reference)
#include <cuda_runtime.h>
#include <math.h>

#define TT 8192
#define KK 1024
#define DD 1024
#define NTH 512
#define NR 8                      // fv replicas (R7-proven operating point)
#define START_TAG 1022
#define STOP_TAG 1023
#define NEGV (-10000.0f)
#define LOG2E 1.4426950408889634f
#define LN2F 0.6931471805599453f

// ---------------- device scratch (no allocs; persistent across calls) ----------------
__device__ __align__(128) unsigned long long g_fvE[2][NR][KK]; // (epoch<<32)|fv_bits
__device__ float g_uc[TT], g_vc[TT], g_uu[TT], g_vu[TT];
__device__ float g_gate[TT + 1];
__device__ unsigned g_sync;       // monotonic counter barrier (never reset)

__device__ __forceinline__ float ex2f(float x) {
    float y; asm("ex2.approx.f32 %0, %1;" : "=f"(y) : "f"(x)); return y;
}
__device__ __forceinline__ float lg2f(float x) {
    float y; asm("lg2.approx.f32 %0, %1;" : "=f"(y) : "f"(x)); return y;
}
__device__ __forceinline__ float ex2s(float x) { return ex2f(fminf(x, 126.0f)); }
__device__ __forceinline__ float lg2s(float v) { return lg2f(fmaxf(v, 1e-37f)); }

__device__ __forceinline__ unsigned long long ldcg_u64(const unsigned long long* p) {
    unsigned long long v;
    asm volatile("ld.global.cg.u64 %0, [%1];" : "=l"(v) : "l"(p) : "memory");
    return v;
}
__device__ __forceinline__ void ldcg_v2(const unsigned long long* p,
                                        unsigned long long& a, unsigned long long& b) {
    asm volatile("ld.global.cg.v2.u64 {%0,%1}, [%2];" : "=l"(a), "=l"(b) : "l"(p) : "memory");
}
__device__ __forceinline__ void stcg_u64(unsigned long long* p, unsigned long long v) {
    asm volatile("st.global.cg.u64 [%0], %1;" :: "l"(p), "l"(v) : "memory");
}
__device__ __forceinline__ unsigned ld_acq(const unsigned* p) {
    unsigned v;
    asm volatile("ld.acquire.gpu.u32 %0, [%1];" : "=r"(v) : "l"(p) : "memory");
    return v;
}

// one-time grid barrier (monotonic counter; replay-safe)
__device__ __forceinline__ void gsync(int G, int tid) {
    __syncthreads();
    if (tid == 0) {
        __threadfence();
        unsigned my = atomicAdd(&g_sync, 1u);
        unsigned goal = my - (my % (unsigned)G) + (unsigned)G;
        while (ld_acq(&g_sync) < goal) { __nanosleep(64); }
    }
    __syncthreads();
}

// ---------------- single persistent kernel (one warp per row) ----------------
__global__ void __launch_bounds__(NTH, 1)
crf_main(const float* __restrict__ feats,
         const float* __restrict__ reps,
         const float* __restrict__ wc,
         const float* __restrict__ wu,
         const float* __restrict__ ti,
         const float* __restrict__ ta,
         const int*   __restrict__ spk,
         float* __restrict__ out) {
    const int G   = gridDim.x;
    const int g   = blockIdx.x;
    const int tid = threadIdx.x;
    const int lane = tid & 31;
    const int wid  = tid >> 5;            // 0..15
    const int r0 = (g * KK) / G;
    const int r1 = ((g + 1) * KK) / G;
    const int R  = r1 - r0;               // rows per CTA (6 or 7 at G=148)
    const bool cw = (wid < R);            // compute warp: one warp per row
    const int row = r0 + wid;
    const int rep = g & (NR - 1);

    // ---- phase 0: warp-distributed gate dot products + fvE init ----
    {
        #pragma unroll
        for (int m = 0; m < 4; m++) {
            int t = g * 16 + wid + G * 16 * m;
            if (t < TT) {
                const float4* rp = (const float4*)(reps + (size_t)t * DD);
                float d0 = 0, d1 = 0, d2 = 0, d3 = 0;
                for (int i = lane; i < 256; i += 32) {
                    float4 r  = rp[i];
                    float4 c0 = ((const float4*)wc)[i];
                    float4 c1 = ((const float4*)wc)[i + 256];
                    float4 u0 = ((const float4*)wu)[i];
                    float4 u1 = ((const float4*)wu)[i + 256];
                    d0 += r.x*c0.x + r.y*c0.y + r.z*c0.z + r.w*c0.w;
                    d1 += r.x*c1.x + r.y*c1.y + r.z*c1.z + r.w*c1.w;
                    d2 += r.x*u0.x + r.y*u0.y + r.z*u0.z + r.w*u0.w;
                    d3 += r.x*u1.x + r.y*u1.y + r.z*u1.z + r.w*u1.w;
                }
                #pragma unroll
                for (int o = 16; o; o >>= 1) {
                    d0 += __shfl_xor_sync(0xffffffffu, d0, o);
                    d1 += __shfl_xor_sync(0xffffffffu, d1, o);
                    d2 += __shfl_xor_sync(0xffffffffu, d2, o);
                    d3 += __shfl_xor_sync(0xffffffffu, d3, o);
                }
                if (lane == 0) { g_uc[t] = d0; g_vc[t] = d1; g_uu[t] = d2; g_vu[t] = d3; }
            }
        }
        if (g == 0) {
            #pragma unroll
            for (int k = 0; k < 2; k++) {
                int idx = tid + k * NTH;
                float v0 = (idx == START_TAG) ? 0.0f : NEGV * LOG2E;
                #pragma unroll
                for (int r = 0; r < NR; r++) {
                    g_fvE[0][r][idx] = (unsigned long long)__float_as_uint(v0);  // epoch 0
                    g_fvE[1][r][idx] = 0xFFFFFFFF00000000ULL;                    // sentinel
                }
            }
        }
    }
    gsync(G, tid);

    // ---- phase 1: gates ----
    {
        int idx = g * NTH + tid;
        if (idx < TT) {
            int pt = idx ? idx - 1 : 0;
            bool uc_ = (idx > 0) && (spk[idx] != 0);
            float x = uc_ ? (g_uc[pt] + g_vc[idx]) : (g_uu[pt] + g_vu[idx]);
            g_gate[idx] = 1.0f / (1.0f + expf(-x));
        } else if (idx == TT) {
            float x = g_uu[TT - 1] + g_vu[TT - 1];
            g_gate[TT] = 1.0f / (1.0f + expf(-x));
        }
    }
    gsync(G, tid);

    // ---- pin matrix row-slice in registers: lane l owns prev-tags {l+32k} ----
    float ta2r[32], df2r[32];
    if (cw) {
        #pragma unroll
        for (int k = 0; k < 32; k++) {
            int j = lane + 32 * k;
            float a = ta[(size_t)row * KK + j];
            float b = ti[(size_t)row * KK + j];
            ta2r[k] = a * LOG2E;
            df2r[k] = (b - a) * LOG2E;
        }
    } else {
        #pragma unroll
        for (int k = 0; k < 32; k++) { ta2r[k] = 0.0f; df2r[k] = 0.0f; }
    }

    __shared__ float s_gate[TT + 8];
    __shared__ float s_fvp2[2][32][33];   // interleaved+padded: tag j -> [j&31][j>>5]
    __shared__ float s_feat[4][8];
    __shared__ float s_refA[2];           // parity-buffered shift reference
    __shared__ float s_m;

    for (int i = tid; i <= TT; i += NTH) s_gate[i] = g_gate[i];
    float vf = 0.0f;
    if (wid == 15 && lane < R) {          // feats ring owner (never a compute warp)
        s_feat[0][lane] = feats[r0 + lane] * LOG2E;
        s_feat[1][lane] = feats[(size_t)KK + r0 + lane] * LOG2E;
        vf = feats[(size_t)2 * KK + r0 + lane];
    }
    if (tid == 0) { s_refA[0] = 0.0f; s_refA[1] = 0.0f; }
    __syncthreads();

    // ---- main sequential loop: ONE __syncthreads per step ----
    for (int t = 0; t < TT; ++t) {
        const int p = t & 1;
        const unsigned ee = (unsigned)t;

        // feats ring: write slot t+2 from register, issue LDG t+3
        if (wid == 15 && lane < R && (t + 2) < TT) {
            s_feat[(t + 2) & 3][lane] = vf * LOG2E;
            if (t + 3 < TT) vf = feats[(size_t)(t + 3) * KK + r0 + lane];
        }

        // stage: all 512 threads, one 16B vector poll each (R7-proven shape)
        {
            const unsigned long long* bp = &g_fvE[p][rep][2 * tid];
            unsigned long long a0, a1;
            for (;;) {
                ldcg_v2(bp, a0, a1);
                if (((((a0 >> 32) ^ ee) | ((a1 >> 32) ^ ee))) == 0ull) break;
                __nanosleep(32);
            }
            int j0 = 2 * tid, j1 = 2 * tid + 1;
            s_fvp2[p][j0 & 31][j0 >> 5] = __uint_as_float((unsigned)a0);
            s_fvp2[p][j1 & 31][j1 >> 5] = __uint_as_float((unsigned)a1);
        }
        __syncthreads();                              // BAR_S (the only barrier)

        if (cw) {
            const float ref  = s_refA[p];             // parity slot: RAW/WAR via BAR_S chain
            const float gate = s_gate[t];
            float acc = 0.0f;
            #pragma unroll
            for (int k = 0; k < 32; k++) {
                float v = s_fvp2[p][lane][k];         // conflict-free: bank (lane+k)&31
                acc += ex2s((v - ref) + fmaf(gate, df2r[k], ta2r[k]));
            }
            #pragma unroll
            for (int o = 16; o; o >>= 1) acc += __shfl_xor_sync(0xffffffffu, acc, o);
            // total on all 32 lanes: in-warp finalize + lane-parallel publish
            float fvnew = ref + s_feat[t & 3][wid] + lg2s(acc);
            if (wid == 0 && lane == 0) s_refA[p ^ 1] = fvnew;
            if (lane < NR) {
                unsigned long long packed =
                    ((unsigned long long)(ee + 1u) << 32) | __float_as_uint(fvnew);
                stcg_u64(&g_fvE[p ^ 1][lane][row], packed);
            }
        }
        // no trailing bar: s_fvp2[p] rewrite at t+2 is behind BAR_S(t+1), which
        // compute warps join only after finishing reads; s_feat/refA likewise.
    }

    // ---------------- terminal: warp owning STOP row (CTA G-1, warp R-1) ----------------
    if (g == G - 1 && wid == R - 1) {                 // row == STOP_TAG
        const float gT = s_gate[TT];
        float term[32];
        float lm = -3.0e38f;
        #pragma unroll
        for (int k = 0; k < 32; k++) {
            int j = lane + 32 * k;
            unsigned long long pk;
            do { pk = ldcg_u64(&g_fvE[0][rep][j]); }          // TT even -> buffer 0
            while ((unsigned)(pk >> 32) != (unsigned)TT);
            float fvf = __uint_as_float((unsigned)pk);
            term[k] = fvf + fmaf(gT, df2r[k], ta2r[k]);
            lm = fmaxf(lm, term[k]);
        }
        #pragma unroll
        for (int o = 16; o; o >>= 1) lm = fmaxf(lm, __shfl_xor_sync(0xffffffffu, lm, o));
        float s = 0.0f;
        #pragma unroll
        for (int k = 0; k < 32; k++) s += ex2s(term[k] - lm);
        #pragma unroll
        for (int o = 16; o; o >>= 1) s += __shfl_xor_sync(0xffffffffu, s, o);
        if (lane == 0) out[0] = (lm + lg2s(s)) * LN2F;        // back to natural log
    }
    (void)s_m;
}

// ---------------- launch: ONE kernel ----------------
extern "C" void kernel_launch(void* const* d_in, const int* in_sizes, int n_in,
                              void* d_out, int out_size) {
    const float* feats = (const float*)d_in[0];
    const float* reps  = (const float*)d_in[1];
    const float* wc    = (const float*)d_in[2];
    const float* wu    = (const float*)d_in[3];
    const float* ti    = (const float*)d_in[4];
    const float* ta    = (const float*)d_in[5];
    const int*   spk   = (const int*)d_in[6];

    int dev = 0; cudaGetDevice(&dev);
    int sm = 148;
    cudaDeviceGetAttribute(&sm, cudaDevAttrMultiProcessorCount, dev);
    int grid = sm;
    if (grid > 256) grid = 256;
    if (grid < 128) grid = 128;    // row mapping needs <=8 rows/CTA (warps 8-15 stage only)

    crf_main<<<grid, NTH>>>(feats, reps, wc, wu, ti, ta, spk, (float*)d_out);
}